// round 15
// baseline (speedup 1.0000x reference)
#include <cuda_runtime.h>
#include <cuda_bf16.h>
#include <cstdint>

#define NMAX 50000
#define EMAX 800000
#define HID  128

// ---------------- scratch (no allocations allowed) ----------------
__device__ __align__(16) float g_msg [(size_t)NMAX * HID];
__device__ __align__(16) float g_self[(size_t)NMAX * HID];
// B fragments in lane-exact mma order:
// frag = ((half*2 + colblk)*8 + ntg)*8 + ks ; per frag: 32 lanes x uint4{bh0,bh1,bl0,bl1}
__device__ __align__(16) uint32_t g_Bfrag[2 * 2 * 8 * 8 * 32 * 4];   // 128 KB
// CSR-by-dst build
__device__ int g_cnt [NMAX];
__device__ int g_off [NMAX + 1];
__device__ int g_pos [EMAX];     // per-edge slot within its dst bucket
__device__ int g_ssrc[EMAX];

// ---------------- helpers ----------------
__device__ __forceinline__ void split2(float x0, float x1, uint32_t& h, uint32_t& l) {
    uint32_t hp;
    asm("cvt.rn.bf16x2.f32 %0, %1, %2;" : "=r"(hp) : "f"(x1), "f"(x0));
    float h0 = __uint_as_float(hp << 16);
    float h1 = __uint_as_float(hp & 0xFFFF0000u);
    float l0 = x0 - h0;
    float l1 = x1 - h1;
    asm("cvt.rn.bf16x2.f32 %0, %1, %2;" : "=r"(l) : "f"(l1), "f"(l0));
    h = hp;
}

#define MMA_BF16(c, a, b0, b1)                                                  \
    asm volatile("mma.sync.aligned.m16n8k16.row.col.f32.bf16.bf16.f32 "        \
                 "{%0,%1,%2,%3}, {%4,%5,%6,%7}, {%8,%9}, {%0,%1,%2,%3};"       \
                 : "+f"((c)[0]), "+f"((c)[1]), "+f"((c)[2]), "+f"((c)[3])      \
                 : "r"((a)[0]), "r"((a)[1]), "r"((a)[2]), "r"((a)[3]),         \
                   "r"(b0), "r"(b1))

// ---------------- B fragment prep (GEMM stream) ----------------
__global__ void prep_kernel(const float* __restrict__ We, const float* __restrict__ Ws) {
    int t = blockIdx.x * blockDim.x + threadIdx.x;   // 8192 threads
    if (t >= 8192) return;
    int lane = t & 31;
    int ks   = (t >> 5) & 7;
    int ntg  = (t >> 8) & 7;     // col group of 8 within the 128-col half
    int cb   = (t >> 11) & 1;    // col block (64) within half
    int half = (t >> 12) & 1;

    int nrow = cb * 64 + ntg * 8 + (lane >> 2);
    int k0   = ks * 16 + (lane & 3) * 2;
    const float* W = (half ? Ws : We) + (size_t)nrow * HID;

    float2 w0 = *reinterpret_cast<const float2*>(W + k0);
    float2 w1 = *reinterpret_cast<const float2*>(W + k0 + 8);
    uint32_t bh0, bl0, bh1, bl1;
    split2(w0.x, w0.y, bh0, bl0);
    split2(w1.x, w1.y, bh1, bl1);

    int frag = ((half * 2 + cb) * 8 + ntg) * 8 + ks;
    *reinterpret_cast<uint4*>(g_Bfrag + (size_t)frag * 128 + lane * 4) =
        make_uint4(bh0, bh1, bl0, bl1);
}

// ---------------- CSR build (side stream) ----------------
__global__ void zero_cnt(int N) {
    for (int i = blockIdx.x * blockDim.x + threadIdx.x; i < N;
         i += gridDim.x * blockDim.x)
        g_cnt[i] = 0;
}

// hist: count + claim slot (the only atomic in the build)
__global__ void hist_kernel(const int* __restrict__ dst, int E, int N) {
    int i = blockIdx.x * blockDim.x + threadIdx.x;
    if (i >= E) return;
    int d = dst[i];
    if ((unsigned)d < (unsigned)N)
        g_pos[i] = atomicAdd(&g_cnt[d], 1);
}

// Single-block exclusive scan over N counters -> g_off; g_off[N] = total.
__global__ void scan_kernel(int N) {
    __shared__ int wsum[32];
    __shared__ int carry_s;
    int tid = threadIdx.x, lane = tid & 31, w = tid >> 5;
    if (tid == 0) carry_s = 0;
    __syncthreads();
    for (int base = 0; base < N; base += 1024) {
        int i = base + tid;
        int v = (i < N) ? g_cnt[i] : 0;
        int x = v;
#pragma unroll
        for (int o = 1; o < 32; o <<= 1) {
            int y = __shfl_up_sync(0xffffffffu, x, o);
            if (lane >= o) x += y;
        }
        if (lane == 31) wsum[w] = x;
        __syncthreads();
        if (w == 0) {
            int s = wsum[lane];
#pragma unroll
            for (int o = 1; o < 32; o <<= 1) {
                int y = __shfl_up_sync(0xffffffffu, s, o);
                if (lane >= o) s += y;
            }
            wsum[lane] = s;
        }
        __syncthreads();
        int excl = x - v + (w > 0 ? wsum[w - 1] : 0) + carry_s;
        if (i < N) g_off[i] = excl;
        __syncthreads();
        if (tid == 1023) carry_s = excl + v;
        __syncthreads();
    }
    if (tid == 0) g_off[N] = carry_s;
}

// scatter: pure (no atomics) — slot already claimed in hist.
__global__ void scatter_kernel(const int* __restrict__ src,
                               const int* __restrict__ dst, int E, int N) {
    int i = blockIdx.x * blockDim.x + threadIdx.x;
    if (i >= E) return;
    int d = dst[i];
    int s = src[i];
    if ((unsigned)d >= (unsigned)N || (unsigned)s >= (unsigned)N) return;
    g_ssrc[g_off[d] + g_pos[i]] = s;
}

// ---------------- tensor-core GEMM via mma.sync (bf16x3, fragment-layout B) ----------------
// Grid (ceil(M/128), 4): y = half*2 + colblk. CTA: 8 warps; warp tile 32x32.
// Warp layout: wrow = wid&3 (4 x 32 rows), wcol = wid>>2 (2 x 32 cols).
__global__ void __launch_bounds__(256, 2)
gemm_mma(const float* __restrict__ A, const float* __restrict__ bias, int M) {
    const int tid  = threadIdx.x;
    const int lane = tid & 31;
    const int wid  = tid >> 5;
    const int wrow = wid & 3;
    const int wcol = wid >> 2;
    const int half = blockIdx.y >> 1;
    const int cb   = blockIdx.y & 1;
    const int row_base = blockIdx.x * 128 + wrow * 32;
    const int g  = lane >> 2;
    const int t2 = (lane & 3) * 2;

    // This warp's 4 col-groups are ntg = wcol*4 + nt (nt 0..3).
    const uint4* __restrict__ bfrag =
        reinterpret_cast<const uint4*>(
            g_Bfrag + ((size_t)((half * 2 + cb) * 8 + wcol * 4) * 8) * 128) +
        lane;   // + nt*256 + ks*32 in uint4 units

    float acc[2][4][4];
#pragma unroll
    for (int mt = 0; mt < 2; mt++)
#pragma unroll
        for (int nt = 0; nt < 4; nt++)
#pragma unroll
            for (int i = 0; i < 4; i++) acc[mt][nt][i] = 0.f;

#pragma unroll
    for (int ks = 0; ks < 8; ks++) {
        const int k0 = ks * 16;

        uint4 bf[4];
#pragma unroll
        for (int nt = 0; nt < 4; nt++)
            bf[nt] = bfrag[nt * 256 + ks * 32];

        uint32_t ahi[2][4], alo[2][4];
#pragma unroll
        for (int mt = 0; mt < 2; mt++) {
            int rA = row_base + mt * 16 + g;
            int rB = rA + 8;
            float2 v00 = make_float2(0.f, 0.f), v01 = v00, v10 = v00, v11 = v00;
            if (rA < M) {
                const float* p = A + (size_t)rA * HID + k0;
                v00 = *reinterpret_cast<const float2*>(p + t2);
                v01 = *reinterpret_cast<const float2*>(p + 8 + t2);
            }
            if (rB < M) {
                const float* p = A + (size_t)rB * HID + k0;
                v10 = *reinterpret_cast<const float2*>(p + t2);
                v11 = *reinterpret_cast<const float2*>(p + 8 + t2);
            }
            split2(v00.x, v00.y, ahi[mt][0], alo[mt][0]);
            split2(v10.x, v10.y, ahi[mt][1], alo[mt][1]);
            split2(v01.x, v01.y, ahi[mt][2], alo[mt][2]);
            split2(v11.x, v11.y, ahi[mt][3], alo[mt][3]);
        }

#pragma unroll
        for (int nt = 0; nt < 4; nt++) {
#pragma unroll
            for (int mt = 0; mt < 2; mt++) {
                MMA_BF16(acc[mt][nt], ahi[mt], bf[nt].x, bf[nt].y);   // hi*hi
                MMA_BF16(acc[mt][nt], ahi[mt], bf[nt].z, bf[nt].w);   // hi*lo
                MMA_BF16(acc[mt][nt], alo[mt], bf[nt].x, bf[nt].y);   // lo*hi
            }
        }
    }

    float* dstb = half ? g_self : g_msg;
#pragma unroll
    for (int mt = 0; mt < 2; mt++) {
#pragma unroll
        for (int nt = 0; nt < 4; nt++) {
            int col = cb * 64 + wcol * 32 + nt * 8 + t2;
            float bx = 0.f, by = 0.f;
            if (half) {
                float2 bb = *reinterpret_cast<const float2*>(bias + col);
                bx = bb.x; by = bb.y;
            }
            int rA = row_base + mt * 16 + g;
            int rB = rA + 8;
            if (rA < M) {
                float2 o = make_float2(acc[mt][nt][0] + bx, acc[mt][nt][1] + by);
                *reinterpret_cast<float2*>(dstb + (size_t)rA * HID + col) = o;
            }
            if (rB < M) {
                float2 o = make_float2(acc[mt][nt][2] + bx, acc[mt][nt][3] + by);
                *reinterpret_cast<float2*>(dstb + (size_t)rB * HID + col) = o;
            }
        }
    }
}

// ---------------- gather + finalize: warp per dst node, no atomics ----------------
// Block = 64 threads (2 warps) to shrink the straggler penalty from degree variance.
__global__ void gather_finalize(float* __restrict__ out, int N) {
    int warp = (blockIdx.x * blockDim.x + threadIdx.x) >> 5;
    int lane = threadIdx.x & 31;
    if (warp >= N) return;

    int s0  = g_off[warp];
    int s1  = g_off[warp + 1];
    int deg = s1 - s0;

    float4 acc = make_float4(0.f, 0.f, 0.f, 0.f);
    int e = s0;
    for (; e + 8 <= s1; e += 8) {
        int idx[8];
#pragma unroll
        for (int j = 0; j < 8; j++) idx[j] = g_ssrc[e + j];
        float4 v[8];
#pragma unroll
        for (int j = 0; j < 8; j++)
            v[j] = *reinterpret_cast<const float4*>(g_msg + (size_t)idx[j] * HID + lane * 4);
#pragma unroll
        for (int j = 0; j < 8; j++) {
            acc.x += v[j].x; acc.y += v[j].y; acc.z += v[j].z; acc.w += v[j].w;
        }
    }
    for (; e < s1; e++) {
        int i0 = g_ssrc[e];
        float4 v = *reinterpret_cast<const float4*>(g_msg + (size_t)i0 * HID + lane * 4);
        acc.x += v.x; acc.y += v.y; acc.z += v.z; acc.w += v.w;
    }

    float inv = 1.0f / fmaxf((float)deg, 1.0f);
    float4 sf = *reinterpret_cast<const float4*>(g_self + (size_t)warp * HID + lane * 4);
    float4 o;
    o.x = fmaxf(fmaf(acc.x, inv, sf.x), 0.f);
    o.y = fmaxf(fmaf(acc.y, inv, sf.y), 0.f);
    o.z = fmaxf(fmaf(acc.z, inv, sf.z), 0.f);
    o.w = fmaxf(fmaf(acc.w, inv, sf.w), 0.f);
    *reinterpret_cast<float4*>(out + (size_t)warp * HID + lane * 4) = o;
}

// ---------------- launch (two-stream fork/join inside the captured graph) ----------------
static cudaStream_t g_s1 = nullptr;
static cudaEvent_t  g_evF = nullptr, g_evJ = nullptr;

extern "C" void kernel_launch(void* const* d_in, const int* in_sizes, int n_in,
                              void* d_out, int out_size) {
    const float* h   = (const float*)d_in[0];
    const int*   src = (const int*)d_in[1];
    const int*   dst = (const int*)d_in[2];
    const float* We  = (const float*)d_in[3];
    const float* Ws  = (const float*)d_in[4];
    const float* b   = (const float*)d_in[5];
    float* out = (float*)d_out;

    const int N = in_sizes[0] / HID;   // 50000
    const int E = in_sizes[1];         // 800000

    if (!g_s1) {   // first call = uncaptured correctness run
        cudaStreamCreateWithFlags(&g_s1, cudaStreamNonBlocking);
        cudaEventCreateWithFlags(&g_evF, cudaEventDisableTiming);
        cudaEventCreateWithFlags(&g_evJ, cudaEventDisableTiming);
    }

    // fork: side stream builds CSR while main stream runs the GEMM path
    cudaEventRecord(g_evF, 0);
    cudaStreamWaitEvent(g_s1, g_evF, 0);

    zero_cnt<<<98, 512, 0, g_s1>>>(N);
    hist_kernel<<<(E + 255) / 256, 256, 0, g_s1>>>(dst, E, N);
    scan_kernel<<<1, 1024, 0, g_s1>>>(N);
    scatter_kernel<<<(E + 255) / 256, 256, 0, g_s1>>>(src, dst, E, N);
    cudaEventRecord(g_evJ, g_s1);

    // main stream: GEMM path
    prep_kernel<<<32, 256>>>(We, Ws);
    dim3 ggrid((N + 127) / 128, 4);
    gemm_mma<<<ggrid, 256>>>(h, b, N);

    // join, then fused gather+finalize
    cudaStreamWaitEvent(0, g_evJ, 0);
    int blocks = (N * 32 + 63) / 64;   // one warp per node, 2 warps per block
    gather_finalize<<<blocks, 64>>>(out, N);
}

// round 16
// speedup vs baseline: 1.1341x; 1.1341x over previous
#include <cuda_runtime.h>
#include <cuda_bf16.h>
#include <cstdint>

#define NMAX 50000
#define EMAX 800000
#define HID  128

// ---------------- scratch (no allocations allowed) ----------------
__device__ __align__(16) float g_msg [(size_t)NMAX * HID];
__device__ __align__(16) float g_self[(size_t)NMAX * HID];
// A pre-split: per (row, k-pair) a uint2 {bf16x2 hi, bf16x2 lo}; 64 pairs/row
__device__ __align__(16) uint2 g_A2[(size_t)NMAX * 64];
// B fragments in lane-exact mma order:
// frag = ((half*2 + colblk)*8 + ntg)*8 + ks ; per frag: 32 lanes x uint4{bh0,bh1,bl0,bl1}
__device__ __align__(16) uint32_t g_Bfrag[2 * 2 * 8 * 8 * 32 * 4];   // 128 KB
// CSR-by-dst build
__device__ int g_cnt [NMAX];
__device__ int g_off [NMAX + 1];
__device__ int g_pos [EMAX];     // per-edge slot within its dst bucket
__device__ int g_ssrc[EMAX];

// ---------------- helpers ----------------
__device__ __forceinline__ void split2(float x0, float x1, uint32_t& h, uint32_t& l) {
    uint32_t hp;
    asm("cvt.rn.bf16x2.f32 %0, %1, %2;" : "=r"(hp) : "f"(x1), "f"(x0));
    float h0 = __uint_as_float(hp << 16);
    float h1 = __uint_as_float(hp & 0xFFFF0000u);
    float l0 = x0 - h0;
    float l1 = x1 - h1;
    asm("cvt.rn.bf16x2.f32 %0, %1, %2;" : "=r"(l) : "f"(l1), "f"(l0));
    h = hp;
}

#define MMA_BF16(c, a0, a1, a2, a3, b0, b1)                                     \
    asm volatile("mma.sync.aligned.m16n8k16.row.col.f32.bf16.bf16.f32 "        \
                 "{%0,%1,%2,%3}, {%4,%5,%6,%7}, {%8,%9}, {%0,%1,%2,%3};"       \
                 : "+f"((c)[0]), "+f"((c)[1]), "+f"((c)[2]), "+f"((c)[3])      \
                 : "r"(a0), "r"(a1), "r"(a2), "r"(a3), "r"(b0), "r"(b1))

// ---------------- A pre-split: fp32 -> interleaved bf16 hi/lo pairs ----------------
__global__ void split_A(const float* __restrict__ A, int M) {
    int t = blockIdx.x * blockDim.x + threadIdx.x;   // one thread = 8 k's of one row
    int row = t >> 4;
    if (row >= M) return;
    int kc = (t & 15) * 8;
    const float* p = A + (size_t)row * HID + kc;
    float x[8];
    *reinterpret_cast<float4*>(x)     = *reinterpret_cast<const float4*>(p);
    *reinterpret_cast<float4*>(x + 4) = *reinterpret_cast<const float4*>(p + 4);
    uint2 o[4];
#pragma unroll
    for (int i = 0; i < 4; i++)
        split2(x[2 * i], x[2 * i + 1], o[i].x, o[i].y);
    uint2* dst = g_A2 + (size_t)row * 64 + (kc >> 1);
    *reinterpret_cast<uint4*>(dst)     = *reinterpret_cast<const uint4*>(o);
    *reinterpret_cast<uint4*>(dst + 2) = *reinterpret_cast<const uint4*>(o + 2);
}

// ---------------- B fragment prep (GEMM stream) ----------------
__global__ void prep_kernel(const float* __restrict__ We, const float* __restrict__ Ws) {
    int t = blockIdx.x * blockDim.x + threadIdx.x;   // 8192 threads
    if (t >= 8192) return;
    int lane = t & 31;
    int ks   = (t >> 5) & 7;
    int ntg  = (t >> 8) & 7;     // col group of 8 within the 128-col half
    int cb   = (t >> 11) & 1;    // col block (64) within half
    int half = (t >> 12) & 1;

    int nrow = cb * 64 + ntg * 8 + (lane >> 2);
    int k0   = ks * 16 + (lane & 3) * 2;
    const float* W = (half ? Ws : We) + (size_t)nrow * HID;

    float2 w0 = *reinterpret_cast<const float2*>(W + k0);
    float2 w1 = *reinterpret_cast<const float2*>(W + k0 + 8);
    uint32_t bh0, bl0, bh1, bl1;
    split2(w0.x, w0.y, bh0, bl0);
    split2(w1.x, w1.y, bh1, bl1);

    int frag = ((half * 2 + cb) * 8 + ntg) * 8 + ks;
    *reinterpret_cast<uint4*>(g_Bfrag + (size_t)frag * 128 + lane * 4) =
        make_uint4(bh0, bh1, bl0, bl1);
}

// ---------------- CSR build (side stream) ----------------
__global__ void zero_cnt(int N) {
    for (int i = blockIdx.x * blockDim.x + threadIdx.x; i < N;
         i += gridDim.x * blockDim.x)
        g_cnt[i] = 0;
}

__global__ void hist_kernel(const int* __restrict__ dst, int E, int N) {
    int i = blockIdx.x * blockDim.x + threadIdx.x;
    if (i >= E) return;
    int d = dst[i];
    if ((unsigned)d < (unsigned)N)
        g_pos[i] = atomicAdd(&g_cnt[d], 1);
}

// Single-block exclusive scan over N counters -> g_off; g_off[N] = total.
__global__ void scan_kernel(int N) {
    __shared__ int wsum[32];
    __shared__ int carry_s;
    int tid = threadIdx.x, lane = tid & 31, w = tid >> 5;
    if (tid == 0) carry_s = 0;
    __syncthreads();
    for (int base = 0; base < N; base += 1024) {
        int i = base + tid;
        int v = (i < N) ? g_cnt[i] : 0;
        int x = v;
#pragma unroll
        for (int o = 1; o < 32; o <<= 1) {
            int y = __shfl_up_sync(0xffffffffu, x, o);
            if (lane >= o) x += y;
        }
        if (lane == 31) wsum[w] = x;
        __syncthreads();
        if (w == 0) {
            int s = wsum[lane];
#pragma unroll
            for (int o = 1; o < 32; o <<= 1) {
                int y = __shfl_up_sync(0xffffffffu, s, o);
                if (lane >= o) s += y;
            }
            wsum[lane] = s;
        }
        __syncthreads();
        int excl = x - v + (w > 0 ? wsum[w - 1] : 0) + carry_s;
        if (i < N) g_off[i] = excl;
        __syncthreads();
        if (tid == 1023) carry_s = excl + v;
        __syncthreads();
    }
    if (tid == 0) g_off[N] = carry_s;
}

__global__ void scatter_kernel(const int* __restrict__ src,
                               const int* __restrict__ dst, int E, int N) {
    int i = blockIdx.x * blockDim.x + threadIdx.x;
    if (i >= E) return;
    int d = dst[i];
    int s = src[i];
    if ((unsigned)d >= (unsigned)N || (unsigned)s >= (unsigned)N) return;
    g_ssrc[g_off[d] + g_pos[i]] = s;
}

// ---------------- tensor-core GEMM (bf16x3, all operands pre-split) ----------------
// Grid (ceil(M/128), 4): y = half*2 + colblk. CTA: 8 warps; warp tile 32x32.
__global__ void __launch_bounds__(256, 2)
gemm_mma(const float* __restrict__ bias, int M) {
    const int tid  = threadIdx.x;
    const int lane = tid & 31;
    const int wid  = tid >> 5;
    const int wrow = wid & 3;
    const int wcol = wid >> 2;
    const int half = blockIdx.y >> 1;
    const int cb   = blockIdx.y & 1;
    const int row_base = blockIdx.x * 128 + wrow * 32;
    const int g  = lane >> 2;
    const int q  = lane & 3;
    const int t2 = q * 2;

    const uint4* __restrict__ bfrag =
        reinterpret_cast<const uint4*>(
            g_Bfrag + ((size_t)((half * 2 + cb) * 8 + wcol * 4) * 8) * 128) +
        lane;   // + nt*256 + ks*32 in uint4 units

    // Clamp fragment rows (OOB rows produce garbage but are never stored).
    int rA0 = row_base + g;        if (rA0 >= M) rA0 = M - 1;
    int rB0 = row_base + g + 8;    if (rB0 >= M) rB0 = M - 1;
    int rA1 = row_base + 16 + g;   if (rA1 >= M) rA1 = M - 1;
    int rB1 = row_base + 24 + g;   if (rB1 >= M) rB1 = M - 1;
    const uint2* __restrict__ pA0 = g_A2 + (size_t)rA0 * 64 + q;
    const uint2* __restrict__ pB0 = g_A2 + (size_t)rB0 * 64 + q;
    const uint2* __restrict__ pA1 = g_A2 + (size_t)rA1 * 64 + q;
    const uint2* __restrict__ pB1 = g_A2 + (size_t)rB1 * 64 + q;

    float acc[2][4][4];
#pragma unroll
    for (int mt = 0; mt < 2; mt++)
#pragma unroll
        for (int nt = 0; nt < 4; nt++)
#pragma unroll
            for (int i = 0; i < 4; i++) acc[mt][nt][i] = 0.f;

#pragma unroll
    for (int ks = 0; ks < 8; ks++) {
        // B: 4 coalesced LDG.128
        uint4 bf[4];
#pragma unroll
        for (int nt = 0; nt < 4; nt++)
            bf[nt] = bfrag[nt * 256 + ks * 32];

        // A: 8 LDG.64, hi+lo arrive together; no conversion ALU.
        uint2 a00 = pA0[ks * 8];       // mt0: rows g,   k pair q
        uint2 a01 = pB0[ks * 8];       // mt0: rows g+8
        uint2 a02 = pA0[ks * 8 + 4];   // mt0: k+8 half
        uint2 a03 = pB0[ks * 8 + 4];
        uint2 a10 = pA1[ks * 8];       // mt1
        uint2 a11 = pB1[ks * 8];
        uint2 a12 = pA1[ks * 8 + 4];
        uint2 a13 = pB1[ks * 8 + 4];

#pragma unroll
        for (int nt = 0; nt < 4; nt++) {
            // mt = 0
            MMA_BF16(acc[0][nt], a00.x, a01.x, a02.x, a03.x, bf[nt].x, bf[nt].y); // hi*hi
            MMA_BF16(acc[0][nt], a00.x, a01.x, a02.x, a03.x, bf[nt].z, bf[nt].w); // hi*lo
            MMA_BF16(acc[0][nt], a00.y, a01.y, a02.y, a03.y, bf[nt].x, bf[nt].y); // lo*hi
            // mt = 1
            MMA_BF16(acc[1][nt], a10.x, a11.x, a12.x, a13.x, bf[nt].x, bf[nt].y);
            MMA_BF16(acc[1][nt], a10.x, a11.x, a12.x, a13.x, bf[nt].z, bf[nt].w);
            MMA_BF16(acc[1][nt], a10.y, a11.y, a12.y, a13.y, bf[nt].x, bf[nt].y);
        }
    }

    float* dstb = half ? g_self : g_msg;
#pragma unroll
    for (int mt = 0; mt < 2; mt++) {
#pragma unroll
        for (int nt = 0; nt < 4; nt++) {
            int col = cb * 64 + wcol * 32 + nt * 8 + t2;
            float bx = 0.f, by = 0.f;
            if (half) {
                float2 bb = *reinterpret_cast<const float2*>(bias + col);
                bx = bb.x; by = bb.y;
            }
            int rA = row_base + mt * 16 + g;
            int rB = rA + 8;
            if (rA < M) {
                float2 o = make_float2(acc[mt][nt][0] + bx, acc[mt][nt][1] + by);
                *reinterpret_cast<float2*>(dstb + (size_t)rA * HID + col) = o;
            }
            if (rB < M) {
                float2 o = make_float2(acc[mt][nt][2] + bx, acc[mt][nt][3] + by);
                *reinterpret_cast<float2*>(dstb + (size_t)rB * HID + col) = o;
            }
        }
    }
}

// ---------------- gather + finalize: warp per dst node, no atomics ----------------
__global__ void gather_finalize(float* __restrict__ out, int N) {
    int warp = (blockIdx.x * blockDim.x + threadIdx.x) >> 5;
    int lane = threadIdx.x & 31;
    if (warp >= N) return;

    int s0  = g_off[warp];
    int s1  = g_off[warp + 1];
    int deg = s1 - s0;

    float4 acc = make_float4(0.f, 0.f, 0.f, 0.f);
    int e = s0;
    for (; e + 8 <= s1; e += 8) {
        int idx[8];
#pragma unroll
        for (int j = 0; j < 8; j++) idx[j] = g_ssrc[e + j];
        float4 v[8];
#pragma unroll
        for (int j = 0; j < 8; j++)
            v[j] = *reinterpret_cast<const float4*>(g_msg + (size_t)idx[j] * HID + lane * 4);
#pragma unroll
        for (int j = 0; j < 8; j++) {
            acc.x += v[j].x; acc.y += v[j].y; acc.z += v[j].z; acc.w += v[j].w;
        }
    }
    for (; e < s1; e++) {
        int i0 = g_ssrc[e];
        float4 v = *reinterpret_cast<const float4*>(g_msg + (size_t)i0 * HID + lane * 4);
        acc.x += v.x; acc.y += v.y; acc.z += v.z; acc.w += v.w;
    }

    float inv = 1.0f / fmaxf((float)deg, 1.0f);
    float4 sf = *reinterpret_cast<const float4*>(g_self + (size_t)warp * HID + lane * 4);
    float4 o;
    o.x = fmaxf(fmaf(acc.x, inv, sf.x), 0.f);
    o.y = fmaxf(fmaf(acc.y, inv, sf.y), 0.f);
    o.z = fmaxf(fmaf(acc.z, inv, sf.z), 0.f);
    o.w = fmaxf(fmaf(acc.w, inv, sf.w), 0.f);
    *reinterpret_cast<float4*>(out + (size_t)warp * HID + lane * 4) = o;
}

// ---------------- launch (two-stream fork/join inside the captured graph) ----------------
static cudaStream_t g_s1 = nullptr;
static cudaEvent_t  g_evF = nullptr, g_evJ = nullptr;

extern "C" void kernel_launch(void* const* d_in, const int* in_sizes, int n_in,
                              void* d_out, int out_size) {
    const float* h   = (const float*)d_in[0];
    const int*   src = (const int*)d_in[1];
    const int*   dst = (const int*)d_in[2];
    const float* We  = (const float*)d_in[3];
    const float* Ws  = (const float*)d_in[4];
    const float* b   = (const float*)d_in[5];
    float* out = (float*)d_out;

    const int N = in_sizes[0] / HID;   // 50000
    const int E = in_sizes[1];         // 800000

    if (!g_s1) {   // first call = uncaptured correctness run
        cudaStreamCreateWithFlags(&g_s1, cudaStreamNonBlocking);
        cudaEventCreateWithFlags(&g_evF, cudaEventDisableTiming);
        cudaEventCreateWithFlags(&g_evJ, cudaEventDisableTiming);
    }

    // fork: side stream builds CSR while main stream runs the GEMM path
    cudaEventRecord(g_evF, 0);
    cudaStreamWaitEvent(g_s1, g_evF, 0);

    zero_cnt<<<98, 512, 0, g_s1>>>(N);
    hist_kernel<<<(E + 255) / 256, 256, 0, g_s1>>>(dst, E, N);
    scan_kernel<<<1, 1024, 0, g_s1>>>(N);
    scatter_kernel<<<(E + 255) / 256, 256, 0, g_s1>>>(src, dst, E, N);
    cudaEventRecord(g_evJ, g_s1);

    // main stream: A split + B prep + GEMM
    prep_kernel<<<32, 256>>>(We, Ws);
    split_A<<<(N * 16 + 255) / 256, 256>>>(h, N);
    dim3 ggrid((N + 127) / 128, 4);
    gemm_mma<<<ggrid, 256>>>(b, N);

    // join, then fused gather+finalize
    cudaStreamWaitEvent(0, g_evJ, 0);
    int blocks = (N * 32 + 63) / 64;   // one warp per node, 2 warps per block
    gather_finalize<<<blocks, 64>>>(out, N);
}

// round 17
// speedup vs baseline: 1.2254x; 1.0805x over previous
#include <cuda_runtime.h>
#include <cuda_bf16.h>
#include <cstdint>

#define NMAX 50000
#define EMAX 800000
#define HID  128

// ---------------- scratch (no allocations allowed) ----------------
__device__ __align__(16) __nv_bfloat16 g_msgb[(size_t)NMAX * HID];   // bf16 messages
__device__ __align__(16) float g_self[(size_t)NMAX * HID];
// A pre-split: per (row, k-pair) a uint2 {bf16x2 hi, bf16x2 lo}; 64 pairs/row
__device__ __align__(16) uint2 g_A2[(size_t)NMAX * 64];
// B fragments in lane-exact mma order:
// frag = ((half*2 + colblk)*8 + ntg)*8 + ks ; per frag: 32 lanes x uint4{bh0,bh1,bl0,bl1}
__device__ __align__(16) uint32_t g_Bfrag[2 * 2 * 8 * 8 * 32 * 4];   // 128 KB
// CSR-by-dst build
__device__ int g_cnt [NMAX];
__device__ int g_off [NMAX + 1];
__device__ int g_pos [EMAX];     // per-edge slot within its dst bucket
__device__ int g_ssrc[EMAX];

// ---------------- helpers ----------------
__device__ __forceinline__ void split2(float x0, float x1, uint32_t& h, uint32_t& l) {
    uint32_t hp;
    asm("cvt.rn.bf16x2.f32 %0, %1, %2;" : "=r"(hp) : "f"(x1), "f"(x0));
    float h0 = __uint_as_float(hp << 16);
    float h1 = __uint_as_float(hp & 0xFFFF0000u);
    float l0 = x0 - h0;
    float l1 = x1 - h1;
    asm("cvt.rn.bf16x2.f32 %0, %1, %2;" : "=r"(l) : "f"(l1), "f"(l0));
    h = hp;
}
__device__ __forceinline__ uint32_t pack_bf16x2(float lo, float hi) {
    uint32_t r;
    asm("cvt.rn.bf16x2.f32 %0, %1, %2;" : "=r"(r) : "f"(hi), "f"(lo));
    return r;   // low half = lo (lower address), high half = hi
}

#define MMA_BF16(c, a0, a1, a2, a3, b0, b1)                                     \
    asm volatile("mma.sync.aligned.m16n8k16.row.col.f32.bf16.bf16.f32 "        \
                 "{%0,%1,%2,%3}, {%4,%5,%6,%7}, {%8,%9}, {%0,%1,%2,%3};"       \
                 : "+f"((c)[0]), "+f"((c)[1]), "+f"((c)[2]), "+f"((c)[3])      \
                 : "r"(a0), "r"(a1), "r"(a2), "r"(a3), "r"(b0), "r"(b1))

// ---------------- A pre-split: fp32 -> interleaved bf16 hi/lo pairs ----------------
__global__ void split_A(const float* __restrict__ A, int M) {
    int t = blockIdx.x * blockDim.x + threadIdx.x;   // one thread = 8 k's of one row
    int row = t >> 4;
    if (row >= M) return;
    int kc = (t & 15) * 8;
    const float* p = A + (size_t)row * HID + kc;
    float x[8];
    *reinterpret_cast<float4*>(x)     = *reinterpret_cast<const float4*>(p);
    *reinterpret_cast<float4*>(x + 4) = *reinterpret_cast<const float4*>(p + 4);
    uint2 o[4];
#pragma unroll
    for (int i = 0; i < 4; i++)
        split2(x[2 * i], x[2 * i + 1], o[i].x, o[i].y);
    uint2* dst = g_A2 + (size_t)row * 64 + (kc >> 1);
    *reinterpret_cast<uint4*>(dst)     = *reinterpret_cast<const uint4*>(o);
    *reinterpret_cast<uint4*>(dst + 2) = *reinterpret_cast<const uint4*>(o + 2);
}

// ---------------- B fragment prep (GEMM stream) ----------------
__global__ void prep_kernel(const float* __restrict__ We, const float* __restrict__ Ws) {
    int t = blockIdx.x * blockDim.x + threadIdx.x;   // 8192 threads
    if (t >= 8192) return;
    int lane = t & 31;
    int ks   = (t >> 5) & 7;
    int ntg  = (t >> 8) & 7;
    int cb   = (t >> 11) & 1;
    int half = (t >> 12) & 1;

    int nrow = cb * 64 + ntg * 8 + (lane >> 2);
    int k0   = ks * 16 + (lane & 3) * 2;
    const float* W = (half ? Ws : We) + (size_t)nrow * HID;

    float2 w0 = *reinterpret_cast<const float2*>(W + k0);
    float2 w1 = *reinterpret_cast<const float2*>(W + k0 + 8);
    uint32_t bh0, bl0, bh1, bl1;
    split2(w0.x, w0.y, bh0, bl0);
    split2(w1.x, w1.y, bh1, bl1);

    int frag = ((half * 2 + cb) * 8 + ntg) * 8 + ks;
    *reinterpret_cast<uint4*>(g_Bfrag + (size_t)frag * 128 + lane * 4) =
        make_uint4(bh0, bh1, bl0, bl1);
}

// ---------------- CSR build (side stream) ----------------
__global__ void zero_cnt(int N) {
    for (int i = blockIdx.x * blockDim.x + threadIdx.x; i < N;
         i += gridDim.x * blockDim.x)
        g_cnt[i] = 0;
}

__global__ void hist_kernel(const int* __restrict__ dst, int E, int N) {
    int i = blockIdx.x * blockDim.x + threadIdx.x;
    if (i >= E) return;
    int d = dst[i];
    if ((unsigned)d < (unsigned)N)
        g_pos[i] = atomicAdd(&g_cnt[d], 1);
}

// Single-block exclusive scan over N counters -> g_off; g_off[N] = total.
__global__ void scan_kernel(int N) {
    __shared__ int wsum[32];
    __shared__ int carry_s;
    int tid = threadIdx.x, lane = tid & 31, w = tid >> 5;
    if (tid == 0) carry_s = 0;
    __syncthreads();
    for (int base = 0; base < N; base += 1024) {
        int i = base + tid;
        int v = (i < N) ? g_cnt[i] : 0;
        int x = v;
#pragma unroll
        for (int o = 1; o < 32; o <<= 1) {
            int y = __shfl_up_sync(0xffffffffu, x, o);
            if (lane >= o) x += y;
        }
        if (lane == 31) wsum[w] = x;
        __syncthreads();
        if (w == 0) {
            int s = wsum[lane];
#pragma unroll
            for (int o = 1; o < 32; o <<= 1) {
                int y = __shfl_up_sync(0xffffffffu, s, o);
                if (lane >= o) s += y;
            }
            wsum[lane] = s;
        }
        __syncthreads();
        int excl = x - v + (w > 0 ? wsum[w - 1] : 0) + carry_s;
        if (i < N) g_off[i] = excl;
        __syncthreads();
        if (tid == 1023) carry_s = excl + v;
        __syncthreads();
    }
    if (tid == 0) g_off[N] = carry_s;
}

__global__ void scatter_kernel(const int* __restrict__ src,
                               const int* __restrict__ dst, int E, int N) {
    int i = blockIdx.x * blockDim.x + threadIdx.x;
    if (i >= E) return;
    int d = dst[i];
    int s = src[i];
    if ((unsigned)d >= (unsigned)N || (unsigned)s >= (unsigned)N) return;
    g_ssrc[g_off[d] + g_pos[i]] = s;
}

// ---------------- tensor-core GEMM (bf16x3, all operands pre-split) ----------------
// Grid (ceil(M/128), 4): y = half*2 + colblk. CTA: 8 warps; warp tile 32x32.
// half==0 -> bf16 msg output; half==1 -> fp32 self output (+bias).
__global__ void __launch_bounds__(256, 2)
gemm_mma(const float* __restrict__ bias, int M) {
    const int tid  = threadIdx.x;
    const int lane = tid & 31;
    const int wid  = tid >> 5;
    const int wrow = wid & 3;
    const int wcol = wid >> 2;
    const int half = blockIdx.y >> 1;
    const int cb   = blockIdx.y & 1;
    const int row_base = blockIdx.x * 128 + wrow * 32;
    const int g  = lane >> 2;
    const int q  = lane & 3;
    const int t2 = q * 2;

    const uint4* __restrict__ bfrag =
        reinterpret_cast<const uint4*>(
            g_Bfrag + ((size_t)((half * 2 + cb) * 8 + wcol * 4) * 8) * 128) +
        lane;   // + nt*256 + ks*32 in uint4 units

    // Clamp fragment rows (OOB rows produce garbage but are never stored).
    int rA0 = row_base + g;        if (rA0 >= M) rA0 = M - 1;
    int rB0 = row_base + g + 8;    if (rB0 >= M) rB0 = M - 1;
    int rA1 = row_base + 16 + g;   if (rA1 >= M) rA1 = M - 1;
    int rB1 = row_base + 24 + g;   if (rB1 >= M) rB1 = M - 1;
    const uint2* __restrict__ pA0 = g_A2 + (size_t)rA0 * 64 + q;
    const uint2* __restrict__ pB0 = g_A2 + (size_t)rB0 * 64 + q;
    const uint2* __restrict__ pA1 = g_A2 + (size_t)rA1 * 64 + q;
    const uint2* __restrict__ pB1 = g_A2 + (size_t)rB1 * 64 + q;

    float acc[2][4][4];
#pragma unroll
    for (int mt = 0; mt < 2; mt++)
#pragma unroll
        for (int nt = 0; nt < 4; nt++)
#pragma unroll
            for (int i = 0; i < 4; i++) acc[mt][nt][i] = 0.f;

#pragma unroll
    for (int ks = 0; ks < 8; ks++) {
        uint4 bf[4];
#pragma unroll
        for (int nt = 0; nt < 4; nt++)
            bf[nt] = bfrag[nt * 256 + ks * 32];

        uint2 a00 = pA0[ks * 8];
        uint2 a01 = pB0[ks * 8];
        uint2 a02 = pA0[ks * 8 + 4];
        uint2 a03 = pB0[ks * 8 + 4];
        uint2 a10 = pA1[ks * 8];
        uint2 a11 = pB1[ks * 8];
        uint2 a12 = pA1[ks * 8 + 4];
        uint2 a13 = pB1[ks * 8 + 4];

#pragma unroll
        for (int nt = 0; nt < 4; nt++) {
            MMA_BF16(acc[0][nt], a00.x, a01.x, a02.x, a03.x, bf[nt].x, bf[nt].y); // hi*hi
            MMA_BF16(acc[0][nt], a00.x, a01.x, a02.x, a03.x, bf[nt].z, bf[nt].w); // hi*lo
            MMA_BF16(acc[0][nt], a00.y, a01.y, a02.y, a03.y, bf[nt].x, bf[nt].y); // lo*hi
            MMA_BF16(acc[1][nt], a10.x, a11.x, a12.x, a13.x, bf[nt].x, bf[nt].y);
            MMA_BF16(acc[1][nt], a10.x, a11.x, a12.x, a13.x, bf[nt].z, bf[nt].w);
            MMA_BF16(acc[1][nt], a10.y, a11.y, a12.y, a13.y, bf[nt].x, bf[nt].y);
        }
    }

    if (half) {
        // self: fp32 + bias
#pragma unroll
        for (int mt = 0; mt < 2; mt++) {
#pragma unroll
            for (int nt = 0; nt < 4; nt++) {
                int col = cb * 64 + wcol * 32 + nt * 8 + t2;
                float2 bb = *reinterpret_cast<const float2*>(bias + col);
                int rA = row_base + mt * 16 + g;
                int rB = rA + 8;
                if (rA < M) {
                    float2 o = make_float2(acc[mt][nt][0] + bb.x, acc[mt][nt][1] + bb.y);
                    *reinterpret_cast<float2*>(g_self + (size_t)rA * HID + col) = o;
                }
                if (rB < M) {
                    float2 o = make_float2(acc[mt][nt][2] + bb.x, acc[mt][nt][3] + bb.y);
                    *reinterpret_cast<float2*>(g_self + (size_t)rB * HID + col) = o;
                }
            }
        }
    } else {
        // msg: pack to bf16
        uint32_t* mb = reinterpret_cast<uint32_t*>(g_msgb);
#pragma unroll
        for (int mt = 0; mt < 2; mt++) {
#pragma unroll
            for (int nt = 0; nt < 4; nt++) {
                int col = cb * 64 + wcol * 32 + nt * 8 + t2;
                int rA = row_base + mt * 16 + g;
                int rB = rA + 8;
                if (rA < M)
                    mb[((size_t)rA * HID + col) >> 1] = pack_bf16x2(acc[mt][nt][0], acc[mt][nt][1]);
                if (rB < M)
                    mb[((size_t)rB * HID + col) >> 1] = pack_bf16x2(acc[mt][nt][2], acc[mt][nt][3]);
            }
        }
    }
}

// ---------------- gather + finalize: warp per dst node, bf16 messages ----------------
__global__ void gather_finalize(float* __restrict__ out, int N) {
    int warp = (blockIdx.x * blockDim.x + threadIdx.x) >> 5;
    int lane = threadIdx.x & 31;
    if (warp >= N) return;

    int s0  = g_off[warp];
    int s1  = g_off[warp + 1];
    int deg = s1 - s0;

    // lane covers 4 bf16 columns: one uint2 (8B) per row; 32 lanes = 256B/row.
    const uint2* msgb = reinterpret_cast<const uint2*>(g_msgb) ;   // 8B units
    float a0 = 0.f, a1 = 0.f, a2 = 0.f, a3 = 0.f;
    int e = s0;
    for (; e + 8 <= s1; e += 8) {
        int idx[8];
#pragma unroll
        for (int j = 0; j < 8; j++) idx[j] = g_ssrc[e + j];
        uint2 v[8];
#pragma unroll
        for (int j = 0; j < 8; j++)
            v[j] = msgb[(size_t)idx[j] * (HID / 4) + lane];
#pragma unroll
        for (int j = 0; j < 8; j++) {
            a0 += __uint_as_float(v[j].x << 16);
            a1 += __uint_as_float(v[j].x & 0xFFFF0000u);
            a2 += __uint_as_float(v[j].y << 16);
            a3 += __uint_as_float(v[j].y & 0xFFFF0000u);
        }
    }
    for (; e < s1; e++) {
        uint2 v = msgb[(size_t)g_ssrc[e] * (HID / 4) + lane];
        a0 += __uint_as_float(v.x << 16);
        a1 += __uint_as_float(v.x & 0xFFFF0000u);
        a2 += __uint_as_float(v.y << 16);
        a3 += __uint_as_float(v.y & 0xFFFF0000u);
    }

    float inv = 1.0f / fmaxf((float)deg, 1.0f);
    float4 sf = *reinterpret_cast<const float4*>(g_self + (size_t)warp * HID + lane * 4);
    float4 o;
    o.x = fmaxf(fmaf(a0, inv, sf.x), 0.f);
    o.y = fmaxf(fmaf(a1, inv, sf.y), 0.f);
    o.z = fmaxf(fmaf(a2, inv, sf.z), 0.f);
    o.w = fmaxf(fmaf(a3, inv, sf.w), 0.f);
    *reinterpret_cast<float4*>(out + (size_t)warp * HID + lane * 4) = o;
}

// ---------------- launch (two-stream fork/join inside the captured graph) ----------------
static cudaStream_t g_s1 = nullptr;
static cudaEvent_t  g_evF = nullptr, g_evJ = nullptr;

extern "C" void kernel_launch(void* const* d_in, const int* in_sizes, int n_in,
                              void* d_out, int out_size) {
    const float* h   = (const float*)d_in[0];
    const int*   src = (const int*)d_in[1];
    const int*   dst = (const int*)d_in[2];
    const float* We  = (const float*)d_in[3];
    const float* Ws  = (const float*)d_in[4];
    const float* b   = (const float*)d_in[5];
    float* out = (float*)d_out;

    const int N = in_sizes[0] / HID;   // 50000
    const int E = in_sizes[1];         // 800000

    if (!g_s1) {   // first call = uncaptured correctness run
        cudaStreamCreateWithFlags(&g_s1, cudaStreamNonBlocking);
        cudaEventCreateWithFlags(&g_evF, cudaEventDisableTiming);
        cudaEventCreateWithFlags(&g_evJ, cudaEventDisableTiming);
    }

    // fork: side stream builds CSR while main stream runs the GEMM path
    cudaEventRecord(g_evF, 0);
    cudaStreamWaitEvent(g_s1, g_evF, 0);

    zero_cnt<<<98, 512, 0, g_s1>>>(N);
    hist_kernel<<<(E + 255) / 256, 256, 0, g_s1>>>(dst, E, N);
    scan_kernel<<<1, 1024, 0, g_s1>>>(N);
    scatter_kernel<<<(E + 255) / 256, 256, 0, g_s1>>>(src, dst, E, N);
    cudaEventRecord(g_evJ, g_s1);

    // main stream: A split + B prep + GEMM
    prep_kernel<<<32, 256>>>(We, Ws);
    split_A<<<(N * 16 + 255) / 256, 256>>>(h, N);
    dim3 ggrid((N + 127) / 128, 4);
    gemm_mma<<<ggrid, 256>>>(b, N);

    // join, then fused gather+finalize
    cudaStreamWaitEvent(0, g_evJ, 0);
    int blocks = (N * 32 + 63) / 64;   // one warp per node, 2 warps per block
    gather_finalize<<<blocks, 64>>>(out, N);
}